// round 5
// baseline (speedup 1.0000x reference)
#include <cuda_runtime.h>
#include <cuda_bf16.h>
#include <math.h>

// ---------------- Problem dims ----------------
#define BB 512
#define TT 512
#define VV 50000
#define EE 100
#define HH 40

typedef unsigned long long u64;

// ---------------- f32x2 packed helpers ----------------
__device__ __forceinline__ u64 f2u2(float x, float y) {
    u64 u; asm("mov.b64 %0, {%1,%2};" : "=l"(u) : "f"(x), "f"(y)); return u;
}
__device__ __forceinline__ u64 fma2(u64 a, u64 b, u64 c) {
    u64 d; asm("fma.rn.f32x2 %0, %1, %2, %3;" : "=l"(d) : "l"(a), "l"(b), "l"(c)); return d;
}
__device__ __forceinline__ u64 add2(u64 a, u64 b) {
    u64 d; asm("add.rn.f32x2 %0, %1, %2;" : "=l"(d) : "l"(a), "l"(b)); return d;
}
__device__ __forceinline__ float2 u2f2(u64 u) {
    float lo, hi; asm("mov.b64 {%0,%1}, %2;" : "=f"(lo), "=f"(hi) : "l"(u));
    return make_float2(lo, hi);
}

__device__ __forceinline__ float sigf(float x) {
    return __fdividef(1.f, 1.f + __expf(-x));
}
__device__ __forceinline__ float tanh_fast(float x) {
    float a = fminf(fmaxf(-2.f * x, -80.f), 80.f);
    float e = __expf(a);
    return __fdividef(1.f - e, 1.f + e);
}

// ---------------- Device scratch ----------------
__device__ __align__(16) float g_embW0[VV * 240];            // layer0 input gates per vocab id
__device__ __align__(16) float g_out0[BB * TT * 80];         // layer0 out, [b][t][fwd40|bwd40]
__device__ __align__(16) float g_gx1[(size_t)BB * TT * 240]; // layer1 precomputed input gates
__device__ __align__(16) float g_Wih0T[EE * 240];
__device__ __align__(16) float g_bih0cat[240];
__device__ __align__(16) float g_Wih1T[80 * 240];
__device__ __align__(16) float g_bih1cat[240];
// gate-owner packed Whh: [dir][j][gate(r,z,n)][k2][2]  (u64 pairs)
__device__ __align__(16) float g_Whh0P[2 * 40 * 3 * 20 * 2];
__device__ __align__(16) float g_Whh1P[2 * 40 * 3 * 20 * 2];
__device__ __align__(16) float g_fc1WT[320 * 128];
__device__ float g_hf0[BB * HH], g_hb0[BB * HH], g_hf1[BB * HH], g_hb1[BB * HH];
__device__ float g_avgp[BB * 80], g_maxp[BB * 80];
__device__ int g_perm[BB];

// ---------------- Prep: transpose / pack all weights ----------------
__global__ void prep_weights(
    const float* __restrict__ Wih0f, const float* __restrict__ Whh0f,
    const float* __restrict__ bih0f,
    const float* __restrict__ Wih0b, const float* __restrict__ Whh0b,
    const float* __restrict__ bih0b,
    const float* __restrict__ Wih1f, const float* __restrict__ Whh1f,
    const float* __restrict__ bih1f,
    const float* __restrict__ Wih1b, const float* __restrict__ Whh1b,
    const float* __restrict__ bih1b,
    const float* __restrict__ fc1_W)
{
    int g = blockIdx.x * blockDim.x + threadIdx.x;
    int NT = gridDim.x * blockDim.x;
    for (int i = g; i < EE * 240; i += NT) {
        int k = i / 240, j = i % 240;
        g_Wih0T[i] = (j < 120) ? Wih0f[j * EE + k] : Wih0b[(j - 120) * EE + k];
    }
    for (int i = g; i < 80 * 240; i += NT) {
        int k = i / 240, j = i % 240;
        g_Wih1T[i] = (j < 120) ? Wih1f[j * 80 + k] : Wih1b[(j - 120) * 80 + k];
    }
    for (int i = g; i < 240; i += NT) {
        g_bih0cat[i] = (i < 120) ? bih0f[i] : bih0b[i - 120];
        g_bih1cat[i] = (i < 120) ? bih1f[i] : bih1b[i - 120];
    }
    // gate-owner packs: idx = ((((dir*40 + j)*3 + gate)*20 + k2)*2 + c)
    for (int i = g; i < 2 * 40 * 3 * 20 * 2; i += NT) {
        int c = i & 1;
        int t = i >> 1;
        int k2 = t % 20;
        int gate = (t / 20) % 3;
        int jj = (t / 60) % 40;
        int dir = t / 2400;
        int src = (gate * 40 + jj) * 40 + 2 * k2 + c;
        g_Whh0P[i] = (dir ? Whh0b : Whh0f)[src];
        g_Whh1P[i] = (dir ? Whh1b : Whh1f)[src];
    }
    for (int i = g; i < 320 * 128; i += NT) {
        int k = i / 128, q = i % 128;
        g_fc1WT[i] = fc1_W[q * 320 + k];
    }
}

// ---------------- Length sort (descending) for load balance ----------------
__global__ void sort_kernel(const int* __restrict__ lens)
{
    __shared__ int L[BB];
    int b = threadIdx.x;
    int lb = lens[b];
    L[b] = lb;
    __syncthreads();
    int r = 0;
    #pragma unroll 8
    for (int i = 0; i < BB; i++) {
        int li = L[i];
        r += (li > lb) || (li == lb && i < b);
    }
    g_perm[r] = b;
}

// ---------------- embW GEMM: [50000,100] x [100,240] + bias ----------------
__global__ void __launch_bounds__(256) embw_kernel(const float* __restrict__ emb)
{
    int j = threadIdx.x;
    int v0 = blockIdx.x * 64;
    int rows = VV - v0; if (rows > 64) rows = 64;
    __shared__ __align__(16) float A_s[20][68];

    u64 acc[32];
    float bias = (j < 240) ? g_bih0cat[j] : 0.f;
    u64 binit = f2u2(bias, bias);
    #pragma unroll
    for (int i = 0; i < 32; i++) acc[i] = binit;

    for (int k0 = 0; k0 < EE; k0 += 20) {
        __syncthreads();
        for (int idx = threadIdx.x; idx < 64 * 20; idx += 256) {
            int r = idx / 20, k = idx % 20;
            A_s[k][r] = (r < rows) ? emb[(size_t)(v0 + r) * EE + k0 + k] : 0.f;
        }
        __syncthreads();
        if (j < 240) {
            #pragma unroll
            for (int k = 0; k < 20; k++) {
                float wv = g_Wih0T[(k0 + k) * 240 + j];
                u64 ww = f2u2(wv, wv);
                const ulonglong2* ap = (const ulonglong2*)(&A_s[k][0]);
                #pragma unroll
                for (int p = 0; p < 16; p++) {
                    ulonglong2 a = ap[p];
                    acc[2 * p + 0] = fma2(a.x, ww, acc[2 * p + 0]);
                    acc[2 * p + 1] = fma2(a.y, ww, acc[2 * p + 1]);
                }
            }
        }
    }
    if (j < 240) {
        #pragma unroll
        for (int i = 0; i < 32; i++) {
            float2 v = u2f2(acc[i]);
            int r = 2 * i;
            if (r < rows)     g_embW0[(size_t)(v0 + r) * 240 + j] = v.x;
            if (r + 1 < rows) g_embW0[(size_t)(v0 + r + 1) * 240 + j] = v.y;
        }
    }
}

// ---------------- gx1 GEMM: [valid rows,80] x [80,240] + bias ----------------
__global__ void __launch_bounds__(256) gx1_kernel(const int* __restrict__ lens)
{
    int b = blockIdx.x;
    int t0 = blockIdx.y * 64;
    int len = lens[b];
    if (t0 >= len) return;
    int rows = len - t0; if (rows > 64) rows = 64;
    int tid = threadIdx.x;
    __shared__ __align__(16) float Xt[80][68];   // [k][r]

    // stage full K=80 with transpose, coalesced float4 reads
    const float4* xb = (const float4*)(g_out0 + ((size_t)b * TT + t0) * 80);
    for (int idx = tid; idx < 64 * 20; idx += 256) {
        int r = idx / 20, c4 = idx % 20;
        float4 v = (r < rows) ? xb[r * 20 + c4] : make_float4(0.f, 0.f, 0.f, 0.f);
        Xt[4 * c4 + 0][r] = v.x;
        Xt[4 * c4 + 1][r] = v.y;
        Xt[4 * c4 + 2][r] = v.z;
        Xt[4 * c4 + 3][r] = v.w;
    }
    __syncthreads();

    int j = tid;
    if (j < 240) {
        u64 acc[32];
        float bias = g_bih1cat[j];
        u64 binit = f2u2(bias, bias);
        #pragma unroll
        for (int i = 0; i < 32; i++) acc[i] = binit;

        #pragma unroll 4
        for (int k = 0; k < 80; k++) {
            float wv = g_Wih1T[k * 240 + j];
            u64 ww = f2u2(wv, wv);
            const ulonglong2* ap = (const ulonglong2*)(&Xt[k][0]);
            #pragma unroll
            for (int p = 0; p < 16; p++) {
                ulonglong2 a = ap[p];
                acc[2 * p + 0] = fma2(a.x, ww, acc[2 * p + 0]);
                acc[2 * p + 1] = fma2(a.y, ww, acc[2 * p + 1]);
            }
        }
        float* ob = g_gx1 + ((size_t)b * TT + t0) * 240 + j;
        #pragma unroll
        for (int i = 0; i < 32; i++) {
            float2 v = u2f2(acc[i]);
            int r = 2 * i;
            if (r < rows)     ob[(size_t)r * 240] = v.x;
            if (r + 1 < rows) ob[(size_t)(r + 1) * 240] = v.y;
        }
    }
}

// ---------------- Layer 0: gate-owner recurrence, 1 barrier/step ----------------
// block 128 = two 64-thread halves (dir 0 / dir 1) of the same batch, named barriers
__global__ void __launch_bounds__(128, 3) gru_layer0(
    const int* __restrict__ text, const int* __restrict__ lens,
    const float* __restrict__ bhh0f, const float* __restrict__ bhh0b)
{
    int b = g_perm[blockIdx.x];
    int tid = threadIdx.x;
    int half = tid >> 6;          // direction
    int j = tid & 63;             // owner if j<40
    __shared__ int toks[TT];
    __shared__ __align__(16) float h_s[2][2][48];  // [dir][buf][40 padded]

    int len = lens[b];
    for (int i = tid; i < len; i += 128) toks[i] = text[b * TT + i];

    u64 wr[20], wz[20], wn[20];
    float bhr = 0.f, bhz = 0.f, bhn = 0.f;
    {
        int jj = (j < 40) ? j : 0;
        const u64* wp = (const u64*)g_Whh0P + (size_t)(half * 40 + jj) * 60;
        if (j < 40) {
            #pragma unroll
            for (int k = 0; k < 20; k++) { wr[k] = wp[k]; wz[k] = wp[20 + k]; wn[k] = wp[40 + k]; }
            const float* bhh = half ? bhh0b : bhh0f;
            bhr = bhh[j]; bhz = bhh[40 + j]; bhn = bhh[80 + j];
            h_s[half][0][j] = 0.f;
        }
    }
    __syncthreads();   // toks + h init visible to both halves

    int t0 = half ? (len - 1) : 0;
    int td = half ? -1 : 1;
    const float* embW = g_embW0 + half * 120;

    float gr0 = 0.f, gz0 = 0.f, gn0 = 0.f, gr1 = 0.f, gz1 = 0.f, gn1 = 0.f;
    if (j < 40) {
        const float* e0 = embW + (size_t)toks[t0] * 240;
        gr0 = e0[j]; gz0 = e0[40 + j]; gn0 = e0[80 + j];
        if (len > 1) {
            const float* e1 = embW + (size_t)toks[t0 + td] * 240;
            gr1 = e1[j]; gz1 = e1[40 + j]; gn1 = e1[80 + j];
        }
    }
    float hreg = 0.f;
    float* outp = g_out0 + ((size_t)b * TT + t0) * 80 + half * 40 + ((j < 40) ? j : 0);
    int ostep = td * 80;
    int buf = 0;
    int bid = half + 1;

    for (int s = 0; s < len; s++) {
        float gr2 = 0.f, gz2 = 0.f, gn2 = 0.f;
        if (j < 40 && s + 2 < len) {
            const float* e2 = embW + (size_t)toks[t0 + (s + 2) * td] * 240;
            gr2 = e2[j]; gz2 = e2[40 + j]; gn2 = e2[80 + j];
        }
        if (j < 40) {
            const ulonglong2* hq = (const ulonglong2*)h_s[half][buf];
            u64 ar0 = f2u2(bhr, 0.f), ar1 = 0ull;
            u64 az0 = f2u2(bhz, 0.f), az1 = 0ull;
            u64 an0 = f2u2(bhn, 0.f), an1 = 0ull;
            #pragma unroll
            for (int q = 0; q < 10; q++) {
                ulonglong2 hv = hq[q];
                ar0 = fma2(wr[2 * q], hv.x, ar0); ar1 = fma2(wr[2 * q + 1], hv.y, ar1);
                az0 = fma2(wz[2 * q], hv.x, az0); az1 = fma2(wz[2 * q + 1], hv.y, az1);
                an0 = fma2(wn[2 * q], hv.x, an0); an1 = fma2(wn[2 * q + 1], hv.y, an1);
            }
            float2 fr = u2f2(add2(ar0, ar1));
            float2 fz = u2f2(add2(az0, az1));
            float2 fn = u2f2(add2(an0, an1));
            float r = sigf(gr0 + fr.x + fr.y);
            float z = sigf(gz0 + fz.x + fz.y);
            float n = tanh_fast(fmaf(r, fn.x + fn.y, gn0));
            float hn = fmaf(z, hreg - n, n);
            hreg = hn;
            h_s[half][buf ^ 1][j] = hn;
            *outp = hn;
            outp += ostep;
        }
        asm volatile("bar.sync %0, 64;" :: "r"(bid) : "memory");
        buf ^= 1;
        gr0 = gr1; gz0 = gz1; gn0 = gn1;
        gr1 = gr2; gz1 = gz2; gn1 = gn2;
    }
    if (j < 40) (half ? g_hb0 : g_hf0)[b * HH + j] = hreg;
}

// ---------------- Layer 1: gate-owner recurrence + fused pooling ----------------
__global__ void __launch_bounds__(128, 3) gru_layer1(
    const int* __restrict__ lens,
    const float* __restrict__ bhh1f, const float* __restrict__ bhh1b)
{
    int b = g_perm[blockIdx.x];
    int tid = threadIdx.x;
    int half = tid >> 6;
    int j = tid & 63;
    __shared__ __align__(16) float h_s[2][2][48];

    int len = lens[b];
    u64 wr[20], wz[20], wn[20];
    float bhr = 0.f, bhz = 0.f, bhn = 0.f;
    {
        int jj = (j < 40) ? j : 0;
        const u64* wp = (const u64*)g_Whh1P + (size_t)(half * 40 + jj) * 60;
        if (j < 40) {
            #pragma unroll
            for (int k = 0; k < 20; k++) { wr[k] = wp[k]; wz[k] = wp[20 + k]; wn[k] = wp[40 + k]; }
            const float* bhh = half ? bhh1b : bhh1f;
            bhr = bhh[j]; bhz = bhh[40 + j]; bhn = bhh[80 + j];
            h_s[half][0][j] = 0.f;
        }
    }
    __syncthreads();

    int t0 = half ? (len - 1) : 0;
    int td = half ? -1 : 1;
    const float* gxb = g_gx1 + ((size_t)b * TT) * 240 + half * 120;

    float gr0 = 0.f, gz0 = 0.f, gn0 = 0.f, gr1 = 0.f, gz1 = 0.f, gn1 = 0.f;
    if (j < 40) {
        const float* e0 = gxb + (size_t)t0 * 240;
        gr0 = e0[j]; gz0 = e0[40 + j]; gn0 = e0[80 + j];
        if (len > 1) {
            const float* e1 = gxb + (size_t)(t0 + td) * 240;
            gr1 = e1[j]; gz1 = e1[40 + j]; gn1 = e1[80 + j];
        }
    }
    float hreg = 0.f;
    float sum_p = 0.f, max_p = -1e30f;
    int buf = 0;
    int bid = half + 1;

    for (int s = 0; s < len; s++) {
        float gr2 = 0.f, gz2 = 0.f, gn2 = 0.f;
        if (j < 40 && s + 2 < len) {
            const float* e2 = gxb + (size_t)(t0 + (s + 2) * td) * 240;
            gr2 = e2[j]; gz2 = e2[40 + j]; gn2 = e2[80 + j];
        }
        if (j < 40) {
            const ulonglong2* hq = (const ulonglong2*)h_s[half][buf];
            u64 ar0 = f2u2(bhr, 0.f), ar1 = 0ull;
            u64 az0 = f2u2(bhz, 0.f), az1 = 0ull;
            u64 an0 = f2u2(bhn, 0.f), an1 = 0ull;
            #pragma unroll
            for (int q = 0; q < 10; q++) {
                ulonglong2 hv = hq[q];
                ar0 = fma2(wr[2 * q], hv.x, ar0); ar1 = fma2(wr[2 * q + 1], hv.y, ar1);
                az0 = fma2(wz[2 * q], hv.x, az0); az1 = fma2(wz[2 * q + 1], hv.y, az1);
                an0 = fma2(wn[2 * q], hv.x, an0); an1 = fma2(wn[2 * q + 1], hv.y, an1);
            }
            float2 fr = u2f2(add2(ar0, ar1));
            float2 fz = u2f2(add2(az0, az1));
            float2 fn = u2f2(add2(an0, an1));
            float r = sigf(gr0 + fr.x + fr.y);
            float z = sigf(gz0 + fz.x + fz.y);
            float n = tanh_fast(fmaf(r, fn.x + fn.y, gn0));
            float hn = fmaf(z, hreg - n, n);
            hreg = hn;
            h_s[half][buf ^ 1][j] = hn;
            sum_p += hn;
            max_p = fmaxf(max_p, hn);
        }
        asm volatile("bar.sync %0, 64;" :: "r"(bid) : "memory");
        buf ^= 1;
        gr0 = gr1; gz0 = gz1; gn0 = gn1;
        gr1 = gr2; gz1 = gz2; gn1 = gn2;
    }
    if (j < 40) {
        g_avgp[b * 80 + half * 40 + j] = sum_p * __fdividef(1.f, (float)len);
        g_maxp[b * 80 + half * 40 + j] = max_p;
        (half ? g_hb1 : g_hf1)[b * HH + j] = hreg;
    }
}

// ---------------- Head: pool_cat -> fc1 -> leaky -> fc2 ----------------
__global__ void __launch_bounds__(128) fc_kernel(
    const float* __restrict__ fc1_b, const float* __restrict__ fc2_W,
    const float* __restrict__ fc2_b, float* __restrict__ out)
{
    int b = blockIdx.x, j = threadIdx.x;
    __shared__ float cat[320];
    for (int i = j; i < 320; i += 128) {
        float v;
        if (i < 40)       v = g_hb1[b * 40 + i];
        else if (i < 80)  v = g_hf1[b * 40 + (i - 40)];
        else if (i < 120) v = g_hb0[b * 40 + (i - 80)];
        else if (i < 160) v = g_hf0[b * 40 + (i - 120)];
        else if (i < 240) v = g_avgp[b * 80 + (i - 160)];
        else              v = g_maxp[b * 80 + (i - 240)];
        cat[i] = v;
    }
    __syncthreads();
    float acc = fc1_b[j];
    #pragma unroll 8
    for (int k = 0; k < 320; k++)
        acc = fmaf(g_fc1WT[k * 128 + j], cat[k], acc);
    float h = (acc >= 0.f) ? acc : 0.01f * acc;
    float p = h * fc2_W[j];
    #pragma unroll
    for (int o = 16; o > 0; o >>= 1) p += __shfl_down_sync(0xffffffffu, p, o);
    __shared__ float red[4];
    if ((j & 31) == 0) red[j >> 5] = p;
    __syncthreads();
    if (j == 0) out[b] = (red[0] + red[1] + red[2] + red[3]) + fc2_b[0];
}

// ---------------- Launch ----------------
extern "C" void kernel_launch(void* const* d_in, const int* in_sizes, int n_in,
                              void* d_out, int out_size)
{
    const int*   text     = (const int*)d_in[0];
    const int*   text_len = (const int*)d_in[1];
    const float* emb      = (const float*)d_in[2];
    const float* Wih0f = (const float*)d_in[3];
    const float* Whh0f = (const float*)d_in[4];
    const float* bih0f = (const float*)d_in[5];
    const float* bhh0f = (const float*)d_in[6];
    const float* Wih0b = (const float*)d_in[7];
    const float* Whh0b = (const float*)d_in[8];
    const float* bih0b = (const float*)d_in[9];
    const float* bhh0b = (const float*)d_in[10];
    const float* Wih1f = (const float*)d_in[11];
    const float* Whh1f = (const float*)d_in[12];
    const float* bih1f = (const float*)d_in[13];
    const float* bhh1f = (const float*)d_in[14];
    const float* Wih1b = (const float*)d_in[15];
    const float* Whh1b = (const float*)d_in[16];
    const float* bih1b = (const float*)d_in[17];
    const float* bhh1b = (const float*)d_in[18];
    const float* fc1_W = (const float*)d_in[19];
    const float* fc1_b = (const float*)d_in[20];
    const float* fc2_W = (const float*)d_in[21];
    const float* fc2_b = (const float*)d_in[22];
    float* out = (float*)d_out;

    prep_weights<<<160, 256>>>(Wih0f, Whh0f, bih0f, Wih0b, Whh0b, bih0b,
                               Wih1f, Whh1f, bih1f, Wih1b, Whh1b, bih1b, fc1_W);
    sort_kernel<<<1, BB>>>(text_len);
    embw_kernel<<<(VV + 63) / 64, 256>>>(emb);
    gru_layer0<<<BB, 128>>>(text, text_len, bhh0f, bhh0b);
    gx1_kernel<<<dim3(BB, TT / 64), 256>>>(text_len);
    gru_layer1<<<BB, 128>>>(text_len, bhh1f, bhh1b);
    fc_kernel<<<BB, 128>>>(fc1_b, fc2_W, fc2_b, out);
}